// round 6
// baseline (speedup 1.0000x reference)
#include <cuda_runtime.h>
#include <cuda_bf16.h>
#include <cstdint>

// EdgePredictor, factorized:
//   Stage 1: tf32 2-pass GEMM  Y[100000,256] = xhi@W + xlo@W  (fp32 acc,
//            x split to tf32 hi/lo IN REGISTERS; W pre-rounded tf32 in SMEM)
//            g_A = Y[:,:128] + b1 ; g_B = Y[:,128:]
//   Stage 2: out[e] = relu(g_A[row] + g_B[col]) @ W2 + b2   (4 lanes/edge)
// No ldmatrix, no bf16 convert phase: tf32 frags are raw f32 bits loaded by LDS.

#define ND  128
#define MAX_NODES 100000
#define TILE_M 64

__device__ float g_A[(size_t)MAX_NODES * ND];   // 51.2 MB
__device__ float g_B[(size_t)MAX_NODES * ND];   // 51.2 MB

// SMEM layout (dynamic): W image 128K + 2 x 32K raw X buffers + b1
#define SM_W    0          // 131072  W' tf32 image [n=256][k=128] f32, swizzled
#define SM_AR0  131072     // 32768   raw X tile buf 0 (64 x 128 f32), swizzled
#define SM_AR1  163840     // 32768   raw X tile buf 1
#define SM_B1   196608     // 512
#define SMEM_TOTAL 197120

// XOR swizzle for 512-byte rows: byte bits [4:6] ^= row bits [9:11]
#define SWZA(x) ((x) ^ (((x) >> 5) & 0x70))

static __device__ __forceinline__ uint32_t smem_u32(const void* p) {
    uint32_t a;
    asm("{ .reg .u64 t; cvta.to.shared.u64 t, %1; cvt.u32.u64 %0, t; }" : "=r"(a) : "l"(p));
    return a;
}

static __device__ __forceinline__ uint32_t f2tf32(float x) {
    uint32_t r;
    asm("cvt.rna.tf32.f32 %0, %1;" : "=r"(r) : "f"(x));
    return r;
}

#define MMA_TF32(d, a, b)                                                       \
    asm volatile("mma.sync.aligned.m16n8k8.row.col.f32.tf32.tf32.f32 "          \
        "{%0,%1,%2,%3}, {%4,%5,%6,%7}, {%8,%9}, {%0,%1,%2,%3};"                 \
        : "+f"((d)[0]), "+f"((d)[1]), "+f"((d)[2]), "+f"((d)[3])                \
        : "r"((a)[0]), "r"((a)[1]), "r"((a)[2]), "r"((a)[3]),                   \
          "r"((b)[0]), "r"((b)[1]))

#define CP_ASYNC16(dst, src, nbytes)                                            \
    asm volatile("cp.async.cg.shared.global [%0], [%1], 16, %2;"                \
        :: "r"(dst), "l"(src), "r"(nbytes))
#define CP_COMMIT() asm volatile("cp.async.commit_group;" ::: "memory")
#define CP_WAIT0()  asm volatile("cp.async.wait_group 0;" ::: "memory")

// ---------------------------------------------------------------------------
// Stage 1: persistent tf32 GEMM. 512 threads, 16 warps = 2m x 8n,
// CTA tile 64x256, warp tile 32x32. Double-buffered raw X via cp.async.
// Prologue: each CTA builds the tf32 W' image in its own SMEM.
// ---------------------------------------------------------------------------
__global__ __launch_bounds__(512, 1) void gemm_kernel(
    const float* __restrict__ x, const float* __restrict__ W1,
    const float* __restrict__ b1, int nnodes, int ntiles)
{
    extern __shared__ char smem[];
    const uint32_t sb = smem_u32(smem);
    const int tid  = threadIdx.x;
    const int lane = tid & 31;
    const int w    = tid >> 5;
    const int warp_m = w & 1;    // 2 groups of 32 rows
    const int warp_n = w >> 1;   // 8 groups of 32 cols

    // ---- prologue: build W' tf32 image [n][k], 512-B rows, swizzled ----
    // W'[n][k]: n<128 -> W1[k][n] ; n>=128 -> W1[128+k][n-128]
    #pragma unroll
    for (int i = tid; i < 256 * 128; i += 512) {     // i = r*128 + c over W1
        int r = i >> 7, c = i & 127;                 // coalesced read of W1
        int k = (r < 128) ? r : (r - 128);
        int n = (r < 128) ? c : (c + 128);
        uint32_t tv = f2tf32(W1[i]);
        *(uint32_t*)(smem + SM_W + SWZA((uint32_t)(n * 512 + k * 4))) = tv;
    }
    if (tid < 128) ((float*)(smem + SM_B1))[tid] = b1[tid];

    // staging coords: 2048 float4 per tile / 512 threads = 4 each
    const int prow = tid >> 5;          // + it*16
    const int pc4  = tid & 31;

    // ---- prefetch first tile into buf 0 ----
    int tile = blockIdx.x;
    {
        long base = (long)tile * TILE_M;
        #pragma unroll
        for (int it = 0; it < 4; it++) {
            int row = prow + it * 16;
            long node = base + row;
            const char* src = (const char*)(x + node * (long)ND) + pc4 * 16;
            uint32_t dst = sb + SM_AR0 + SWZA((uint32_t)(row * 512 + pc4 * 16));
            int nb = (tile < ntiles && node < nnodes) ? 16 : 0;
            if (nb == 0) src = (const char*)x;
            CP_ASYNC16(dst, src, nb);
        }
        CP_COMMIT();
    }

    int cur = 0;
    for (; tile < ntiles; tile += gridDim.x) {
        const long base = (long)tile * TILE_M;
        const uint32_t arbase = sb + (cur ? SM_AR1 : SM_AR0);

        CP_WAIT0();
        __syncthreads();   // buf[cur] ready; buf[cur^1] free (prev iter done)

        // ---- issue cp.async for tile t+grid into buf[cur^1] ----
        {
            int nxt = tile + gridDim.x;
            long nbase = (long)nxt * TILE_M;
            uint32_t nxtbase = sb + (cur ? SM_AR0 : SM_AR1);
            #pragma unroll
            for (int it = 0; it < 4; it++) {
                int row = prow + it * 16;
                long node = nbase + row;
                const char* src = (const char*)(x + node * (long)ND) + pc4 * 16;
                uint32_t dst = nxtbase + SWZA((uint32_t)(row * 512 + pc4 * 16));
                int nb = (nxt < ntiles && node < nnodes) ? 16 : 0;
                if (nb == 0) src = (const char*)x;
                CP_ASYNC16(dst, src, nb);
            }
            CP_COMMIT();
        }

        // ---- MMA mainloop: acc[2 ms][4 ns][4] ----
        float acc[2][4][4];
        #pragma unroll
        for (int ms = 0; ms < 2; ms++)
            #pragma unroll
            for (int ns = 0; ns < 4; ns++)
                #pragma unroll
                for (int e = 0; e < 4; e++) acc[ms][ns][e] = 0.f;

        const int arow = warp_m * 32 + (lane >> 2);   // A frag row base
        const int acol = (lane & 3);                   // A frag col base
        const int bn   = warp_n * 32 + (lane >> 2);    // B frag n base
        const int bk   = (lane & 3);                   // B frag k base

        #pragma unroll 4
        for (int ks = 0; ks < 16; ks++) {
            const int kc = ks * 8;

            // A frags: raw f32 -> tf32 hi/lo in registers
            uint32_t ahi[2][4], alo[2][4];
            #pragma unroll
            for (int ms = 0; ms < 2; ms++) {
                const int r = arow + ms * 16;
                #pragma unroll
                for (int e = 0; e < 4; e++) {
                    int rr = r + ((e & 1) ? 8 : 0);
                    int cc = kc + acol + ((e & 2) ? 4 : 0);
                    float v = *(const float*)(smem + (arbase - sb)
                              + SWZA((uint32_t)(rr * 512 + cc * 4)));
                    uint32_t h = f2tf32(v);
                    ahi[ms][e] = h;
                    alo[ms][e] = f2tf32(v - __uint_as_float(h));
                }
            }
            // B frags (already tf32-rounded in image)
            uint32_t bv[4][2];
            #pragma unroll
            for (int ns = 0; ns < 4; ns++) {
                int n = bn + ns * 8;
                bv[ns][0] = *(const uint32_t*)(smem + SM_W
                            + SWZA((uint32_t)(n * 512 + (kc + bk) * 4)));
                bv[ns][1] = *(const uint32_t*)(smem + SM_W
                            + SWZA((uint32_t)(n * 512 + (kc + bk + 4) * 4)));
            }
            #pragma unroll
            for (int ms = 0; ms < 2; ms++)
                #pragma unroll
                for (int ns = 0; ns < 4; ns++) {
                    MMA_TF32(acc[ms][ns], ahi[ms], bv[ns]);
                    MMA_TF32(acc[ms][ns], alo[ms], bv[ns]);
                }
        }

        // ---- epilogue ----
        float* dstbase = (warp_n < 4) ? g_A : g_B;
        const int colbase = (warp_n & 3) * 32 + 2 * (lane & 3);
        const int rowbase = warp_m * 32 + (lane >> 2);
        const float* b1s = (const float*)(smem + SM_B1);

        #pragma unroll
        for (int ms = 0; ms < 2; ms++) {
            #pragma unroll
            for (int ns = 0; ns < 4; ns++) {
                const int col = colbase + ns * 8;
                float bias0 = 0.f, bias1 = 0.f;
                if (warp_n < 4) { bias0 = b1s[col]; bias1 = b1s[col + 1]; }
                long node0 = base + rowbase + ms * 16;
                if (node0 < nnodes)
                    *(float2*)(dstbase + node0 * (long)ND + col) =
                        make_float2(acc[ms][ns][0] + bias0, acc[ms][ns][1] + bias1);
                long node1 = node0 + 8;
                if (node1 < nnodes)
                    *(float2*)(dstbase + node1 * (long)ND + col) =
                        make_float2(acc[ms][ns][2] + bias0, acc[ms][ns][3] + bias1);
            }
        }

        cur ^= 1;
    }
}

// ---------------------------------------------------------------------------
// Stage 2: 4 lanes per edge, 8 edges per warp. Each lane: 32 k's = 8 float4
// pairs (16 independent LDG.128 in flight). 2-level shuffle reduce.
// ---------------------------------------------------------------------------
__global__ __launch_bounds__(256) void edge_kernel(
    const int* __restrict__ ei,        // [2, E] int32
    const float* __restrict__ W2,      // [128, 2]
    const float* __restrict__ b2,      // [2]
    float* __restrict__ out,           // [E, 2]
    int E)
{
    __shared__ float w2a[ND];
    __shared__ float w2b[ND];
    const int tid = threadIdx.x;
    if (tid < ND) {
        w2a[tid] = W2[tid * 2 + 0];
        w2b[tid] = W2[tid * 2 + 1];
    }
    __syncthreads();

    const int lane = tid & 31;
    const int t    = lane & 3;
    const int sub  = lane >> 2;
    const float b20 = __ldg(b2), b21 = __ldg(b2 + 1);

    const int warp   = (blockIdx.x * blockDim.x + tid) >> 5;
    const int nwarps = (gridDim.x * blockDim.x) >> 5;

    for (int eb = warp * 8; eb < E; eb += nwarps * 8) {
        const int e = eb + sub;       // E % 8 == 0
        const int r = __ldg(ei + e);
        const int c = __ldg(ei + (size_t)E + e);

        const float4* pa = (const float4*)(g_A + (size_t)r * ND) + t * 8;
        const float4* pb = (const float4*)(g_B + (size_t)c * ND) + t * 8;
        const float4* wa = (const float4*)(w2a + t * 32);
        const float4* wb = (const float4*)(w2b + t * 32);

        float o0 = 0.f, o1 = 0.f;
        #pragma unroll
        for (int i = 0; i < 8; i++) {
            const float4 a  = __ldg(pa + i);
            const float4 b  = __ldg(pb + i);
            const float4 va = wa[i];
            const float4 vb = wb[i];
            const float h0 = fmaxf(a.x + b.x, 0.f);
            const float h1 = fmaxf(a.y + b.y, 0.f);
            const float h2 = fmaxf(a.z + b.z, 0.f);
            const float h3 = fmaxf(a.w + b.w, 0.f);
            o0 = fmaf(h0, va.x, fmaf(h1, va.y, fmaf(h2, va.z, fmaf(h3, va.w, o0))));
            o1 = fmaf(h0, vb.x, fmaf(h1, vb.y, fmaf(h2, vb.z, fmaf(h3, vb.w, o1))));
        }

        o0 += __shfl_xor_sync(0xFFFFFFFFu, o0, 1);
        o0 += __shfl_xor_sync(0xFFFFFFFFu, o0, 2);
        o1 += __shfl_xor_sync(0xFFFFFFFFu, o1, 1);
        o1 += __shfl_xor_sync(0xFFFFFFFFu, o1, 2);

        if (t == 0) {
            *(float2*)(out + 2 * (size_t)e) = make_float2(o0 + b20, o1 + b21);
        }
    }
}

// ---------------------------------------------------------------------------
extern "C" void kernel_launch(void* const* d_in, const int* in_sizes, int n_in,
                              void* d_out, int out_size)
{
    const float* x  = (const float*)d_in[0];      // [N,128]
    const int*   ei = (const int*)d_in[1];        // [2,E] int32
    const float* W1 = (const float*)d_in[2];      // [256,128]
    const float* b1 = (const float*)d_in[3];      // [128]
    const float* W2 = (const float*)d_in[4];      // [128,2]
    const float* b2 = (const float*)d_in[5];      // [2]
    float*       out = (float*)d_out;             // [E,2]

    const int nnodes = in_sizes[0] / ND;
    const int E      = in_sizes[1] / 2;
    const int ntiles = (nnodes + TILE_M - 1) / TILE_M;

    cudaFuncSetAttribute(gemm_kernel, cudaFuncAttributeMaxDynamicSharedMemorySize,
                         SMEM_TOTAL);

    gemm_kernel<<<148, 512, SMEM_TOTAL>>>(x, W1, b1, nnodes, ntiles);
    edge_kernel<<<(E + 63) / 64, 256>>>(ei, W2, b2, out, E);
}

// round 7
// speedup vs baseline: 4.4626x; 4.4626x over previous
#include <cuda_runtime.h>
#include <cuda_bf16.h>
#include <cuda_fp16.h>
#include <cstdint>

// EdgePredictor, factorized:
//   Stage 0: prep  W' = [W1_top^T ; W1_bot^T] n-major, split bf16 hi/lo, pre-swizzled.
//   Stage 1: mma.sync bf16 GEMM  Y[100000,256] = Xhi*Whi + Xlo*Whi + Xhi*Wlo (fp32 acc)
//            cp.async pipeline; epilogue stores A=Y[:,:128]+b1, B=Y[:,128:] as FP16.
//   Stage 2: out[e] = relu(A[row] + B[col]) @ W2 + b2, 4 lanes/edge with
//            CONTIGUOUS 64B/instr lane mapping (8 L1 lines/instr, was 32).

#define ND  128
#define MAX_NODES 100000
#define TILE_M 64

__device__ __half g_Ah[(size_t)MAX_NODES * ND];   // 25.6 MB
__device__ __half g_Bh[(size_t)MAX_NODES * ND];   // 25.6 MB
__device__ uint4 g_Whi[4096];   // 64 KB: W' hi [n=256][k=128] bf16, swizzled
__device__ uint4 g_Wlo[4096];   // 64 KB

// SMEM layout (dynamic, 192.5 KB)
#define SM_WHI  0          // 65536
#define SM_WLO  65536      // 65536
#define SM_ARAW 131072     // 32768  raw fp32 X tile (64 x 128 f32)
#define SM_AHI  163840     // 16384  bf16 hi tile
#define SM_ALO  180224     // 16384  bf16 lo tile
#define SM_B1   196608     // 512
#define SMEM_TOTAL 197120

// XOR swizzle for 256-byte rows: chunk bits [4:6] ^= row bits [8:10]
#define SWZ(x) ((x) ^ (((x) >> 4) & 0x70))

static __device__ __forceinline__ uint32_t smem_u32(const void* p) {
    uint32_t a;
    asm("{ .reg .u64 t; cvta.to.shared.u64 t, %1; cvt.u32.u64 %0, t; }" : "=r"(a) : "l"(p));
    return a;
}

#define LDSM4(r, addr)                                                          \
    asm volatile("ldmatrix.sync.aligned.m8n8.x4.shared.b16 {%0,%1,%2,%3}, [%4];"\
        : "=r"((r)[0]), "=r"((r)[1]), "=r"((r)[2]), "=r"((r)[3]) : "r"(addr))

#define MMA16816(d, a, b)                                                       \
    asm volatile("mma.sync.aligned.m16n8k16.row.col.f32.bf16.bf16.f32 "         \
        "{%0,%1,%2,%3}, {%4,%5,%6,%7}, {%8,%9}, {%0,%1,%2,%3};"                 \
        : "+f"((d)[0]), "+f"((d)[1]), "+f"((d)[2]), "+f"((d)[3])                \
        : "r"((a)[0]), "r"((a)[1]), "r"((a)[2]), "r"((a)[3]),                   \
          "r"((b)[0]), "r"((b)[1]))

#define CP_ASYNC16(dst, src, nbytes)                                            \
    asm volatile("cp.async.cg.shared.global [%0], [%1], 16, %2;"                \
        :: "r"(dst), "l"(src), "r"(nbytes))
#define CP_COMMIT() asm volatile("cp.async.commit_group;" ::: "memory")
#define CP_WAIT0()  asm volatile("cp.async.wait_group 0;" ::: "memory")

// ---------------------------------------------------------------------------
// Stage 0: W' hi/lo bf16 images. W'[n][k]: n<128 -> W1[k][n]; else W1[128+k][n-128]
// ---------------------------------------------------------------------------
__global__ void prep_w_kernel(const float* __restrict__ W1) {
    int i = blockIdx.x * blockDim.x + threadIdx.x;
    if (i >= 256 * 128) return;
    int n = i >> 7, k = i & 127;
    float w = (n < 128) ? W1[k * 128 + n] : W1[(128 + k) * 128 + (n - 128)];
    __nv_bfloat16 hi = __float2bfloat16(w);
    __nv_bfloat16 lo = __float2bfloat16(w - __bfloat162float(hi));
    uint32_t sw = SWZ((uint32_t)(n * 256 + k * 2));
    *(__nv_bfloat16*)((char*)g_Whi + sw) = hi;
    *(__nv_bfloat16*)((char*)g_Wlo + sw) = lo;
}

// ---------------------------------------------------------------------------
// Stage 1: persistent pipelined bf16 GEMM (round-5 structure). 512 threads,
// 16 warps (2m x 8n), CTA tile 64x256, warp tile 32x32. FP16 output stores.
// ---------------------------------------------------------------------------
__global__ __launch_bounds__(512, 1) void gemm_kernel(
    const float* __restrict__ x, const float* __restrict__ b1,
    int nnodes, int ntiles)
{
    extern __shared__ char smem[];
    const uint32_t sb = smem_u32(smem);
    const int tid  = threadIdx.x;
    const int lane = tid & 31;
    const int w    = tid >> 5;
    const int warp_m = w & 1;
    const int warp_n = w >> 1;

    {
        uint4* dhi = (uint4*)(smem + SM_WHI);
        uint4* dlo = (uint4*)(smem + SM_WLO);
        #pragma unroll 8
        for (int i = tid; i < 4096; i += 512) { dhi[i] = g_Whi[i]; dlo[i] = g_Wlo[i]; }
        if (tid < 128) ((float*)(smem + SM_B1))[tid] = b1[tid];
    }

    const int prow = tid >> 5;
    const int pc4  = tid & 31;

    const int a_row = (lane & 15);
    const int a_ko  = (lane >> 4) << 4;
    const int b_row = (lane & 7) + ((lane >> 4) << 3);
    const int b_ko  = ((lane >> 3) & 1) << 4;

    int tile = blockIdx.x;
    {
        long base = (long)tile * TILE_M;
        #pragma unroll
        for (int it = 0; it < 4; it++) {
            int row = prow + it * 16;
            long node = base + row;
            const char* src = (const char*)(x + node * (long)ND) + pc4 * 16;
            uint32_t dst = sb + SM_ARAW + row * 512 + pc4 * 16;
            int nb = (tile < ntiles && node < nnodes) ? 16 : 0;
            if (nb == 0) src = (const char*)x;
            CP_ASYNC16(dst, src, nb);
        }
        CP_COMMIT();
    }
    CP_WAIT0();
    __syncthreads();

    for (; tile < ntiles; tile += gridDim.x) {
        const long base = (long)tile * TILE_M;

        // ---- convert staged raw tile -> bf16 hi/lo (swizzled) ----
        #pragma unroll
        for (int it = 0; it < 4; it++) {
            int row = prow + it * 16;
            float4 v = *(const float4*)(smem + SM_ARAW + row * 512 + pc4 * 16);
            __nv_bfloat162 h01 = __floats2bfloat162_rn(v.x, v.y);
            __nv_bfloat162 h23 = __floats2bfloat162_rn(v.z, v.w);
            __nv_bfloat162 l01 = __floats2bfloat162_rn(v.x - __bfloat162float(h01.x),
                                                       v.y - __bfloat162float(h01.y));
            __nv_bfloat162 l23 = __floats2bfloat162_rn(v.z - __bfloat162float(h23.x),
                                                       v.w - __bfloat162float(h23.y));
            uint32_t sw = SWZ((uint32_t)(row * 256 + pc4 * 8));
            uint2 hp, lp;
            hp.x = *(uint32_t*)&h01; hp.y = *(uint32_t*)&h23;
            lp.x = *(uint32_t*)&l01; lp.y = *(uint32_t*)&l23;
            *(uint2*)(smem + SM_AHI + sw) = hp;
            *(uint2*)(smem + SM_ALO + sw) = lp;
        }
        __syncthreads();

        // ---- cp.async next tile (overlaps MMA) ----
        {
            int nxt = tile + gridDim.x;
            long nbase = (long)nxt * TILE_M;
            #pragma unroll
            for (int it = 0; it < 4; it++) {
                int row = prow + it * 16;
                long node = nbase + row;
                const char* src = (const char*)(x + node * (long)ND) + pc4 * 16;
                uint32_t dst = sb + SM_ARAW + row * 512 + pc4 * 16;
                int nb = (nxt < ntiles && node < nnodes) ? 16 : 0;
                if (nb == 0) src = (const char*)x;
                CP_ASYNC16(dst, src, nb);
            }
            CP_COMMIT();
        }

        // ---- compute ----
        float acc[2][4][4];
        #pragma unroll
        for (int ms = 0; ms < 2; ms++)
            #pragma unroll
            for (int ns = 0; ns < 4; ns++)
                #pragma unroll
                for (int e = 0; e < 4; e++) acc[ms][ns][e] = 0.f;

        #pragma unroll
        for (int ks = 0; ks < 8; ks++) {
            uint32_t ah[2][4], al[2][4], bh[8], bl[8];
            #pragma unroll
            for (int ms = 0; ms < 2; ms++) {
                uint32_t ab = SWZ((uint32_t)((warp_m * 32 + ms * 16 + a_row) * 256
                                             + ks * 32 + a_ko));
                LDSM4(ah[ms], sb + SM_AHI + ab);
                LDSM4(al[ms], sb + SM_ALO + ab);
            }
            #pragma unroll
            for (int bj = 0; bj < 2; bj++) {
                uint32_t bb = SWZ((uint32_t)((warp_n * 32 + bj * 16 + b_row) * 256
                                             + ks * 32 + b_ko));
                LDSM4(&bh[bj * 4], sb + SM_WHI + bb);
                LDSM4(&bl[bj * 4], sb + SM_WLO + bb);
            }
            #pragma unroll
            for (int ms = 0; ms < 2; ms++) {
                #pragma unroll
                for (int ns = 0; ns < 4; ns++) {
                    MMA16816(acc[ms][ns], ah[ms], &bh[ns * 2]);
                    MMA16816(acc[ms][ns], al[ms], &bh[ns * 2]);
                    MMA16816(acc[ms][ns], ah[ms], &bl[ns * 2]);
                }
            }
        }

        // ---- epilogue: fp16 stores (half2 = 2 adjacent cols) ----
        __half* dsth = (warp_n < 4) ? g_Ah : g_Bh;
        const int colbase = (warp_n & 3) * 32 + 2 * (lane & 3);
        const int rowbase = warp_m * 32 + (lane >> 2);
        const float* b1s = (const float*)(smem + SM_B1);

        #pragma unroll
        for (int ms = 0; ms < 2; ms++) {
            #pragma unroll
            for (int ns = 0; ns < 4; ns++) {
                const int col = colbase + ns * 8;
                float bias0 = 0.f, bias1 = 0.f;
                if (warp_n < 4) { bias0 = b1s[col]; bias1 = b1s[col + 1]; }
                long node0 = base + rowbase + ms * 16;
                if (node0 < nnodes)
                    *(__half2*)(dsth + node0 * (long)ND + col) =
                        __floats2half2_rn(acc[ms][ns][0] + bias0, acc[ms][ns][1] + bias1);
                long node1 = node0 + 8;
                if (node1 < nnodes)
                    *(__half2*)(dsth + node1 * (long)ND + col) =
                        __floats2half2_rn(acc[ms][ns][2] + bias0, acc[ms][ns][3] + bias1);
            }
        }

        CP_WAIT0();
        __syncthreads();
    }
}

// ---------------------------------------------------------------------------
// Stage 2: 4 lanes/edge, 8 edges/warp, fp16 rows (256 B). Lane t reads chunk
// i*4+t -> 4 lanes cover 64 CONTIGUOUS bytes per instruction (8 lines/instr).
// ---------------------------------------------------------------------------
__global__ __launch_bounds__(256) void edge_kernel(
    const int* __restrict__ ei,        // [2, E] int32
    const float* __restrict__ W2,      // [128, 2]
    const float* __restrict__ b2,      // [2]
    float* __restrict__ out,           // [E, 2]
    int E)
{
    __shared__ float w2a[ND];
    __shared__ float w2b[ND];
    const int tid = threadIdx.x;
    if (tid < ND) {
        w2a[tid] = W2[tid * 2 + 0];
        w2b[tid] = W2[tid * 2 + 1];
    }
    __syncthreads();

    const int lane = tid & 31;
    const int t    = lane & 3;
    const int sub  = lane >> 2;
    const float b20 = __ldg(b2), b21 = __ldg(b2 + 1);
    const __half2 z2 = __float2half2_rn(0.f);

    const int warp   = (blockIdx.x * blockDim.x + tid) >> 5;
    const int nwarps = (gridDim.x * blockDim.x) >> 5;

    const float4* wa4 = (const float4*)w2a;   // 32 float4
    const float4* wb4 = (const float4*)w2b;

    for (int eb = warp * 8; eb < E; eb += nwarps * 8) {
        const int e = eb + sub;       // E % 8 == 0
        const int r = __ldg(ei + e);
        const int c = __ldg(ei + (size_t)E + e);

        const uint4* pa = (const uint4*)(g_Ah + (size_t)r * ND);  // 16 chunks x 8 half
        const uint4* pb = (const uint4*)(g_Bh + (size_t)c * ND);

        float o0 = 0.f, o1 = 0.f;
        #pragma unroll
        for (int i = 0; i < 4; i++) {
            const int ch = i * 4 + t;              // contiguous across 4 lanes
            uint4 a4 = __ldg(pa + ch);
            uint4 b4 = __ldg(pb + ch);
            const float4 walo = wa4[ch * 2], wahi = wa4[ch * 2 + 1];
            const float4 wblo = wb4[ch * 2], wbhi = wb4[ch * 2 + 1];

            const __half2* ap = (const __half2*)&a4;
            const __half2* bp = (const __half2*)&b4;

            float2 f0 = __half22float2(__hmax2(__hadd2(ap[0], bp[0]), z2));
            float2 f1 = __half22float2(__hmax2(__hadd2(ap[1], bp[1]), z2));
            float2 f2 = __half22float2(__hmax2(__hadd2(ap[2], bp[2]), z2));
            float2 f3 = __half22float2(__hmax2(__hadd2(ap[3], bp[3]), z2));

            o0 = fmaf(f0.x, walo.x, fmaf(f0.y, walo.y, o0));
            o0 = fmaf(f1.x, walo.z, fmaf(f1.y, walo.w, o0));
            o0 = fmaf(f2.x, wahi.x, fmaf(f2.y, wahi.y, o0));
            o0 = fmaf(f3.x, wahi.z, fmaf(f3.y, wahi.w, o0));

            o1 = fmaf(f0.x, wblo.x, fmaf(f0.y, wblo.y, o1));
            o1 = fmaf(f1.x, wblo.z, fmaf(f1.y, wblo.w, o1));
            o1 = fmaf(f2.x, wbhi.x, fmaf(f2.y, wbhi.y, o1));
            o1 = fmaf(f3.x, wbhi.z, fmaf(f3.y, wbhi.w, o1));
        }

        o0 += __shfl_xor_sync(0xFFFFFFFFu, o0, 1);
        o0 += __shfl_xor_sync(0xFFFFFFFFu, o0, 2);
        o1 += __shfl_xor_sync(0xFFFFFFFFu, o1, 1);
        o1 += __shfl_xor_sync(0xFFFFFFFFu, o1, 2);

        if (t == 0) {
            *(float2*)(out + 2 * (size_t)e) = make_float2(o0 + b20, o1 + b21);
        }
    }
}

// ---------------------------------------------------------------------------
extern "C" void kernel_launch(void* const* d_in, const int* in_sizes, int n_in,
                              void* d_out, int out_size)
{
    const float* x  = (const float*)d_in[0];      // [N,128]
    const int*   ei = (const int*)d_in[1];        // [2,E] int32
    const float* W1 = (const float*)d_in[2];      // [256,128]
    const float* b1 = (const float*)d_in[3];      // [128]
    const float* W2 = (const float*)d_in[4];      // [128,2]
    const float* b2 = (const float*)d_in[5];      // [2]
    float*       out = (float*)d_out;             // [E,2]

    const int nnodes = in_sizes[0] / ND;
    const int E      = in_sizes[1] / 2;
    const int ntiles = (nnodes + TILE_M - 1) / TILE_M;

    cudaFuncSetAttribute(gemm_kernel, cudaFuncAttributeMaxDynamicSharedMemorySize,
                         SMEM_TOTAL);

    prep_w_kernel<<<128, 256>>>(W1);
    gemm_kernel<<<148, 512, SMEM_TOTAL>>>(x, b1, nnodes, ntiles);
    edge_kernel<<<(E + 63) / 64, 256>>>(ei, W2, b2, out, E);
}

// round 8
// speedup vs baseline: 4.5591x; 1.0216x over previous
#include <cuda_runtime.h>
#include <cuda_bf16.h>
#include <cuda_fp16.h>
#include <cstdint>

// EdgePredictor, factorized:
//   Stage 1: fp16 2-pass GEMM  Y[100000,256] = Xhi@W + Xlo@W  (fp32 acc;
//            X split to fp16 hi/lo -> exact to 2^-22; W single fp16 rounding).
//            W' image built per-CTA in prologue (no prep kernel).
//            Epilogue stores A = Y[:,:128]+b1, B = Y[:,128:] as FP16.
//   Stage 2: out[e] = relu(A[row] + B[col]) @ W2 + b2, 4 lanes/edge,
//            contiguous 64B/instr lane mapping.

#define ND  128
#define MAX_NODES 100000
#define TILE_M 128

__device__ __half g_Ah[(size_t)MAX_NODES * ND];   // 25.6 MB
__device__ __half g_Bh[(size_t)MAX_NODES * ND];   // 25.6 MB

// SMEM layout (dynamic, 192.5 KB)
#define SM_W    0          // 65536  W' fp16 [n=256][k=128], 256B rows, swizzled
#define SM_ARAW 65536      // 65536  raw fp32 X tile (128 x 128 f32)
#define SM_AHI  131072     // 32768  fp16 hi tile (128 x 128), swizzled
#define SM_ALO  163840     // 32768  fp16 lo tile
#define SM_B1   196608     // 512
#define SMEM_TOTAL 197120

// XOR swizzle for 256-byte rows: byte bits [4:6] ^= row bits [8:10]
#define SWZ(x) ((x) ^ (((x) >> 4) & 0x70))

static __device__ __forceinline__ uint32_t smem_u32(const void* p) {
    uint32_t a;
    asm("{ .reg .u64 t; cvta.to.shared.u64 t, %1; cvt.u32.u64 %0, t; }" : "=r"(a) : "l"(p));
    return a;
}

#define LDSM4(r, addr)                                                          \
    asm volatile("ldmatrix.sync.aligned.m8n8.x4.shared.b16 {%0,%1,%2,%3}, [%4];"\
        : "=r"((r)[0]), "=r"((r)[1]), "=r"((r)[2]), "=r"((r)[3]) : "r"(addr))

#define MMA16816F(d, a, b)                                                      \
    asm volatile("mma.sync.aligned.m16n8k16.row.col.f32.f16.f16.f32 "           \
        "{%0,%1,%2,%3}, {%4,%5,%6,%7}, {%8,%9}, {%0,%1,%2,%3};"                 \
        : "+f"((d)[0]), "+f"((d)[1]), "+f"((d)[2]), "+f"((d)[3])                \
        : "r"((a)[0]), "r"((a)[1]), "r"((a)[2]), "r"((a)[3]),                   \
          "r"((b)[0]), "r"((b)[1]))

#define CP_ASYNC16(dst, src, nbytes)                                            \
    asm volatile("cp.async.cg.shared.global [%0], [%1], 16, %2;"                \
        :: "r"(dst), "l"(src), "r"(nbytes))
#define CP_COMMIT() asm volatile("cp.async.commit_group;" ::: "memory")
#define CP_WAIT0()  asm volatile("cp.async.wait_group 0;" ::: "memory")

// ---------------------------------------------------------------------------
// Stage 1: persistent pipelined fp16 GEMM. 512 threads, 16 warps (4m x 4n),
// CTA tile 128x256, warp tile 32x64, 2 passes (Xhi, Xlo).
// ---------------------------------------------------------------------------
__global__ __launch_bounds__(512, 1) void gemm_kernel(
    const float* __restrict__ x, const float* __restrict__ W1,
    const float* __restrict__ b1, int nnodes, int ntiles)
{
    extern __shared__ char smem[];
    const uint32_t sb = smem_u32(smem);
    const int tid  = threadIdx.x;
    const int lane = tid & 31;
    const int w    = tid >> 5;
    const int warp_m = w & 3;    // 4 groups of 32 rows
    const int warp_n = w >> 2;   // 4 groups of 64 cols

    // staging coords: 4096 float4 / 512 threads = 8 each
    const int prow = tid >> 5;          // + it*16
    const int pc4  = tid & 31;

    // ---- prefetch first tile ----
    int tile = blockIdx.x;
    {
        long base = (long)tile * TILE_M;
        #pragma unroll
        for (int it = 0; it < 8; it++) {
            int row = prow + it * 16;
            long node = base + row;
            const char* src = (const char*)(x + node * (long)ND) + pc4 * 16;
            uint32_t dst = sb + SM_ARAW + row * 512 + pc4 * 16;
            int nb = (tile < ntiles && node < nnodes) ? 16 : 0;
            if (nb == 0) src = (const char*)x;
            CP_ASYNC16(dst, src, nb);
        }
        CP_COMMIT();
    }

    // ---- prologue: build W' fp16 image while the first tile loads ----
    // W'[n][k]: n<128 -> W1[k][n] ; n>=128 -> W1[128+k][n-128]
    #pragma unroll
    for (int i = tid; i < 256 * 128; i += 512) {     // coalesced read of W1
        int r = i >> 7, c = i & 127;
        int k = (r < 128) ? r : (r - 128);
        int n = (r < 128) ? c : (c + 128);
        __half hv = __float2half_rn(W1[i]);
        *(__half*)(smem + SM_W + SWZ((uint32_t)(n * 256 + k * 2))) = hv;
    }
    if (tid < 128) ((float*)(smem + SM_B1))[tid] = b1[tid];

    CP_WAIT0();
    __syncthreads();

    // ldmatrix lane address components
    const int a_row = (lane & 15);
    const int a_ko  = (lane >> 4) << 4;
    const int b_row = (lane & 7) + ((lane >> 4) << 3);
    const int b_ko  = ((lane >> 3) & 1) << 4;

    for (; tile < ntiles; tile += gridDim.x) {
        const long base = (long)tile * TILE_M;

        // ---- convert raw tile -> fp16 hi/lo (swizzled) ----
        #pragma unroll
        for (int it = 0; it < 8; it++) {
            int row = prow + it * 16;
            float4 v = *(const float4*)(smem + SM_ARAW + row * 512 + pc4 * 16);
            __half2 h01 = __floats2half2_rn(v.x, v.y);
            __half2 h23 = __floats2half2_rn(v.z, v.w);
            float2 hf01 = __half22float2(h01);
            float2 hf23 = __half22float2(h23);
            __half2 l01 = __floats2half2_rn(v.x - hf01.x, v.y - hf01.y);
            __half2 l23 = __floats2half2_rn(v.z - hf23.x, v.w - hf23.y);
            uint32_t sw = SWZ((uint32_t)(row * 256 + pc4 * 8));
            uint2 hp, lp;
            hp.x = *(uint32_t*)&h01; hp.y = *(uint32_t*)&h23;
            lp.x = *(uint32_t*)&l01; lp.y = *(uint32_t*)&l23;
            *(uint2*)(smem + SM_AHI + sw) = hp;
            *(uint2*)(smem + SM_ALO + sw) = lp;
        }
        __syncthreads();   // AHI/ALO ready; all done reading ARAW

        // ---- cp.async next tile into ARAW (overlaps MMA) ----
        {
            int nxt = tile + gridDim.x;
            long nbase = (long)nxt * TILE_M;
            #pragma unroll
            for (int it = 0; it < 8; it++) {
                int row = prow + it * 16;
                long node = nbase + row;
                const char* src = (const char*)(x + node * (long)ND) + pc4 * 16;
                uint32_t dst = sb + SM_ARAW + row * 512 + pc4 * 16;
                int nb = (nxt < ntiles && node < nnodes) ? 16 : 0;
                if (nb == 0) src = (const char*)x;
                CP_ASYNC16(dst, src, nb);
            }
            CP_COMMIT();
        }

        // ---- compute: acc[2 ms][8 ns][4] ----
        float acc[2][8][4];
        #pragma unroll
        for (int ms = 0; ms < 2; ms++)
            #pragma unroll
            for (int ns = 0; ns < 8; ns++)
                #pragma unroll
                for (int e = 0; e < 4; e++) acc[ms][ns][e] = 0.f;

        #pragma unroll
        for (int ks = 0; ks < 8; ks++) {
            uint32_t ah[2][4], al[2][4], bv[16];
            #pragma unroll
            for (int ms = 0; ms < 2; ms++) {
                uint32_t ab = SWZ((uint32_t)((warp_m * 32 + ms * 16 + a_row) * 256
                                             + ks * 32 + a_ko));
                LDSM4(ah[ms], sb + SM_AHI + ab);
                LDSM4(al[ms], sb + SM_ALO + ab);
            }
            #pragma unroll
            for (int bj = 0; bj < 4; bj++) {
                uint32_t bb = SWZ((uint32_t)((warp_n * 64 + bj * 16 + b_row) * 256
                                             + ks * 32 + b_ko));
                LDSM4(&bv[bj * 4], sb + SM_W + bb);
            }
            #pragma unroll
            for (int ms = 0; ms < 2; ms++) {
                #pragma unroll
                for (int ns = 0; ns < 8; ns++) {
                    MMA16816F(acc[ms][ns], ah[ms], &bv[ns * 2]);   // hi pass
                    MMA16816F(acc[ms][ns], al[ms], &bv[ns * 2]);   // lo pass
                }
            }
        }

        // ---- epilogue: fp16 stores ----
        __half* dsth = (warp_n < 2) ? g_Ah : g_Bh;
        const int colbase = (warp_n & 1) * 64 + 2 * (lane & 3);
        const int rowbase = warp_m * 32 + (lane >> 2);
        const float* b1s = (const float*)(smem + SM_B1);

        #pragma unroll
        for (int ms = 0; ms < 2; ms++) {
            #pragma unroll
            for (int ns = 0; ns < 8; ns++) {
                const int col = colbase + ns * 8;
                float bias0 = 0.f, bias1 = 0.f;
                if (warp_n < 2) { bias0 = b1s[col]; bias1 = b1s[col + 1]; }
                long node0 = base + rowbase + ms * 16;
                if (node0 < nnodes)
                    *(__half2*)(dsth + node0 * (long)ND + col) =
                        __floats2half2_rn(acc[ms][ns][0] + bias0, acc[ms][ns][1] + bias1);
                long node1 = node0 + 8;
                if (node1 < nnodes)
                    *(__half2*)(dsth + node1 * (long)ND + col) =
                        __floats2half2_rn(acc[ms][ns][2] + bias0, acc[ms][ns][3] + bias1);
            }
        }

        CP_WAIT0();
        __syncthreads();
    }
}

// ---------------------------------------------------------------------------
// Stage 2: 4 lanes/edge, 8 edges/warp, fp16 rows (256 B). Lane t reads chunk
// i*4+t -> 4 lanes cover 64 contiguous bytes per instruction.
// ---------------------------------------------------------------------------
__global__ __launch_bounds__(256) void edge_kernel(
    const int* __restrict__ ei,        // [2, E] int32
    const float* __restrict__ W2,      // [128, 2]
    const float* __restrict__ b2,      // [2]
    float* __restrict__ out,           // [E, 2]
    int E)
{
    __shared__ float w2a[ND];
    __shared__ float w2b[ND];
    const int tid = threadIdx.x;
    if (tid < ND) {
        w2a[tid] = W2[tid * 2 + 0];
        w2b[tid] = W2[tid * 2 + 1];
    }
    __syncthreads();

    const int lane = tid & 31;
    const int t    = lane & 3;
    const int sub  = lane >> 2;
    const float b20 = __ldg(b2), b21 = __ldg(b2 + 1);
    const __half2 z2 = __float2half2_rn(0.f);

    const int warp   = (blockIdx.x * blockDim.x + tid) >> 5;
    const int nwarps = (gridDim.x * blockDim.x) >> 5;

    const float4* wa4 = (const float4*)w2a;
    const float4* wb4 = (const float4*)w2b;

    for (int eb = warp * 8; eb < E; eb += nwarps * 8) {
        const int e = eb + sub;       // E % 8 == 0
        const int r = __ldg(ei + e);
        const int c = __ldg(ei + (size_t)E + e);

        const uint4* pa = (const uint4*)(g_Ah + (size_t)r * ND);
        const uint4* pb = (const uint4*)(g_Bh + (size_t)c * ND);

        float o0 = 0.f, o1 = 0.f;
        #pragma unroll
        for (int i = 0; i < 4; i++) {
            const int ch = i * 4 + t;              // contiguous across 4 lanes
            uint4 a4 = __ldg(pa + ch);
            uint4 b4 = __ldg(pb + ch);
            const float4 walo = wa4[ch * 2], wahi = wa4[ch * 2 + 1];
            const float4 wblo = wb4[ch * 2], wbhi = wb4[ch * 2 + 1];

            const __half2* ap = (const __half2*)&a4;
            const __half2* bp = (const __half2*)&b4;

            float2 f0 = __half22float2(__hmax2(__hadd2(ap[0], bp[0]), z2));
            float2 f1 = __half22float2(__hmax2(__hadd2(ap[1], bp[1]), z2));
            float2 f2 = __half22float2(__hmax2(__hadd2(ap[2], bp[2]), z2));
            float2 f3 = __half22float2(__hmax2(__hadd2(ap[3], bp[3]), z2));

            o0 = fmaf(f0.x, walo.x, fmaf(f0.y, walo.y, o0));
            o0 = fmaf(f1.x, walo.z, fmaf(f1.y, walo.w, o0));
            o0 = fmaf(f2.x, wahi.x, fmaf(f2.y, wahi.y, o0));
            o0 = fmaf(f3.x, wahi.z, fmaf(f3.y, wahi.w, o0));

            o1 = fmaf(f0.x, wblo.x, fmaf(f0.y, wblo.y, o1));
            o1 = fmaf(f1.x, wblo.z, fmaf(f1.y, wblo.w, o1));
            o1 = fmaf(f2.x, wbhi.x, fmaf(f2.y, wbhi.y, o1));
            o1 = fmaf(f3.x, wbhi.z, fmaf(f3.y, wbhi.w, o1));
        }

        o0 += __shfl_xor_sync(0xFFFFFFFFu, o0, 1);
        o0 += __shfl_xor_sync(0xFFFFFFFFu, o0, 2);
        o1 += __shfl_xor_sync(0xFFFFFFFFu, o1, 1);
        o1 += __shfl_xor_sync(0xFFFFFFFFu, o1, 2);

        if (t == 0) {
            *(float2*)(out + 2 * (size_t)e) = make_float2(o0 + b20, o1 + b21);
        }
    }
}

// ---------------------------------------------------------------------------
extern "C" void kernel_launch(void* const* d_in, const int* in_sizes, int n_in,
                              void* d_out, int out_size)
{
    const float* x  = (const float*)d_in[0];      // [N,128]
    const int*   ei = (const int*)d_in[1];        // [2,E] int32
    const float* W1 = (const float*)d_in[2];      // [256,128]
    const float* b1 = (const float*)d_in[3];      // [128]
    const float* W2 = (const float*)d_in[4];      // [128,2]
    const float* b2 = (const float*)d_in[5];      // [2]
    float*       out = (float*)d_out;             // [E,2]

    const int nnodes = in_sizes[0] / ND;
    const int E      = in_sizes[1] / 2;
    const int ntiles = (nnodes + TILE_M - 1) / TILE_M;

    cudaFuncSetAttribute(gemm_kernel, cudaFuncAttributeMaxDynamicSharedMemorySize,
                         SMEM_TOTAL);

    gemm_kernel<<<148, 512, SMEM_TOTAL>>>(x, W1, b1, nnodes, ntiles);
    edge_kernel<<<(E + 63) / 64, 256>>>(ei, W2, b2, out, E);
}

// round 9
// speedup vs baseline: 5.5037x; 1.2072x over previous
#include <cuda_runtime.h>
#include <cuda_bf16.h>
#include <cuda_fp16.h>
#include <cstdint>

// EdgePredictor, factorized:
//   Stage 1: fp16 1-pass GEMM  Y[100000,256] = X@W  (fp32 acc; single fp16
//            rounding on X and W — error budget measured: each rounding ~2e-4,
//            storage ~3.5e-4 -> total ~5e-4 < 1e-3).
//            W' image built per-CTA in prologue. A=Y[:,:128]+b1, B=Y[:,128:] as fp16.
//   Stage 2: out[e] = relu(A[row] + B[col]) @ W2 + b2, 4 lanes/edge,
//            contiguous 64B/instr lane mapping.

#define ND  128
#define MAX_NODES 100000
#define TILE_M 128

__device__ __half g_Ah[(size_t)MAX_NODES * ND];   // 25.6 MB
__device__ __half g_Bh[(size_t)MAX_NODES * ND];   // 25.6 MB

// SMEM layout (dynamic, 160.5 KB)
#define SM_W    0          // 65536  W' fp16 [n=256][k=128], 256B rows, swizzled
#define SM_ARAW 65536      // 65536  raw fp32 X tile (128 x 128 f32)
#define SM_AH   131072     // 32768  fp16 X tile (128 x 128), swizzled
#define SM_B1   163840     // 512
#define SMEM_TOTAL 164352

// XOR swizzle for 256-byte rows: byte bits [4:6] ^= row bits [8:10]
#define SWZ(x) ((x) ^ (((x) >> 4) & 0x70))

static __device__ __forceinline__ uint32_t smem_u32(const void* p) {
    uint32_t a;
    asm("{ .reg .u64 t; cvta.to.shared.u64 t, %1; cvt.u32.u64 %0, t; }" : "=r"(a) : "l"(p));
    return a;
}

#define LDSM4(r, addr)                                                          \
    asm volatile("ldmatrix.sync.aligned.m8n8.x4.shared.b16 {%0,%1,%2,%3}, [%4];"\
        : "=r"((r)[0]), "=r"((r)[1]), "=r"((r)[2]), "=r"((r)[3]) : "r"(addr))

#define MMA16816F(d, a, b)                                                      \
    asm volatile("mma.sync.aligned.m16n8k16.row.col.f32.f16.f16.f32 "           \
        "{%0,%1,%2,%3}, {%4,%5,%6,%7}, {%8,%9}, {%0,%1,%2,%3};"                 \
        : "+f"((d)[0]), "+f"((d)[1]), "+f"((d)[2]), "+f"((d)[3])                \
        : "r"((a)[0]), "r"((a)[1]), "r"((a)[2]), "r"((a)[3]),                   \
          "r"((b)[0]), "r"((b)[1]))

#define CP_ASYNC16(dst, src, nbytes)                                            \
    asm volatile("cp.async.cg.shared.global [%0], [%1], 16, %2;"                \
        :: "r"(dst), "l"(src), "r"(nbytes))
#define CP_COMMIT() asm volatile("cp.async.commit_group;" ::: "memory")
#define CP_WAIT0()  asm volatile("cp.async.wait_group 0;" ::: "memory")

// ---------------------------------------------------------------------------
// Stage 1: persistent pipelined fp16 GEMM. 512 threads, 16 warps (4m x 4n),
// CTA tile 128x256, warp tile 32x64, single pass.
// ---------------------------------------------------------------------------
__global__ __launch_bounds__(512, 1) void gemm_kernel(
    const float* __restrict__ x, const float* __restrict__ W1,
    const float* __restrict__ b1, int nnodes, int ntiles)
{
    extern __shared__ char smem[];
    const uint32_t sb = smem_u32(smem);
    const int tid  = threadIdx.x;
    const int lane = tid & 31;
    const int w    = tid >> 5;
    const int warp_m = w & 3;    // 4 groups of 32 rows
    const int warp_n = w >> 2;   // 4 groups of 64 cols

    // staging coords: 4096 float4 / 512 threads = 8 each
    const int prow = tid >> 5;          // + it*16
    const int pc4  = tid & 31;

    // ---- prefetch first tile ----
    int tile = blockIdx.x;
    {
        long base = (long)tile * TILE_M;
        #pragma unroll
        for (int it = 0; it < 8; it++) {
            int row = prow + it * 16;
            long node = base + row;
            const char* src = (const char*)(x + node * (long)ND) + pc4 * 16;
            uint32_t dst = sb + SM_ARAW + row * 512 + pc4 * 16;
            int nb = (tile < ntiles && node < nnodes) ? 16 : 0;
            if (nb == 0) src = (const char*)x;
            CP_ASYNC16(dst, src, nb);
        }
        CP_COMMIT();
    }

    // ---- prologue: build W' fp16 image while first tile loads ----
    // W'[n][k]: n<128 -> W1[k][n] ; n>=128 -> W1[128+k][n-128]
    #pragma unroll
    for (int i = tid; i < 256 * 128; i += 512) {     // coalesced read of W1
        int r = i >> 7, c = i & 127;
        int k = (r < 128) ? r : (r - 128);
        int n = (r < 128) ? c : (c + 128);
        __half hv = __float2half_rn(W1[i]);
        *(__half*)(smem + SM_W + SWZ((uint32_t)(n * 256 + k * 2))) = hv;
    }
    if (tid < 128) ((float*)(smem + SM_B1))[tid] = b1[tid];

    CP_WAIT0();
    __syncthreads();

    // ldmatrix lane address components
    const int a_row = (lane & 15);
    const int a_ko  = (lane >> 4) << 4;
    const int b_row = (lane & 7) + ((lane >> 4) << 3);
    const int b_ko  = ((lane >> 3) & 1) << 4;

    for (; tile < ntiles; tile += gridDim.x) {
        const long base = (long)tile * TILE_M;

        // ---- convert raw tile -> fp16 (swizzled) ----
        #pragma unroll
        for (int it = 0; it < 8; it++) {
            int row = prow + it * 16;
            float4 v = *(const float4*)(smem + SM_ARAW + row * 512 + pc4 * 16);
            __half2 h01 = __floats2half2_rn(v.x, v.y);
            __half2 h23 = __floats2half2_rn(v.z, v.w);
            uint2 hp;
            hp.x = *(uint32_t*)&h01; hp.y = *(uint32_t*)&h23;
            *(uint2*)(smem + SM_AH + SWZ((uint32_t)(row * 256 + pc4 * 8))) = hp;
        }
        __syncthreads();   // AH ready; all done reading ARAW

        // ---- cp.async next tile into ARAW (overlaps MMA) ----
        {
            int nxt = tile + gridDim.x;
            long nbase = (long)nxt * TILE_M;
            #pragma unroll
            for (int it = 0; it < 8; it++) {
                int row = prow + it * 16;
                long node = nbase + row;
                const char* src = (const char*)(x + node * (long)ND) + pc4 * 16;
                uint32_t dst = sb + SM_ARAW + row * 512 + pc4 * 16;
                int nb = (nxt < ntiles && node < nnodes) ? 16 : 0;
                if (nb == 0) src = (const char*)x;
                CP_ASYNC16(dst, src, nb);
            }
            CP_COMMIT();
        }

        // ---- compute: acc[2 ms][8 ns][4] ----
        float acc[2][8][4];
        #pragma unroll
        for (int ms = 0; ms < 2; ms++)
            #pragma unroll
            for (int ns = 0; ns < 8; ns++)
                #pragma unroll
                for (int e = 0; e < 4; e++) acc[ms][ns][e] = 0.f;

        #pragma unroll
        for (int ks = 0; ks < 8; ks++) {
            uint32_t av[2][4], bv[16];
            #pragma unroll
            for (int ms = 0; ms < 2; ms++) {
                uint32_t ab = SWZ((uint32_t)((warp_m * 32 + ms * 16 + a_row) * 256
                                             + ks * 32 + a_ko));
                LDSM4(av[ms], sb + SM_AH + ab);
            }
            #pragma unroll
            for (int bj = 0; bj < 4; bj++) {
                uint32_t bb = SWZ((uint32_t)((warp_n * 64 + bj * 16 + b_row) * 256
                                             + ks * 32 + b_ko));
                LDSM4(&bv[bj * 4], sb + SM_W + bb);
            }
            #pragma unroll
            for (int ms = 0; ms < 2; ms++)
                #pragma unroll
                for (int ns = 0; ns < 8; ns++)
                    MMA16816F(acc[ms][ns], av[ms], &bv[ns * 2]);
        }

        // ---- epilogue: fp16 stores ----
        __half* dsth = (warp_n < 2) ? g_Ah : g_Bh;
        const int colbase = (warp_n & 1) * 64 + 2 * (lane & 3);
        const int rowbase = warp_m * 32 + (lane >> 2);
        const float* b1s = (const float*)(smem + SM_B1);

        #pragma unroll
        for (int ms = 0; ms < 2; ms++) {
            #pragma unroll
            for (int ns = 0; ns < 8; ns++) {
                const int col = colbase + ns * 8;
                float bias0 = 0.f, bias1 = 0.f;
                if (warp_n < 2) { bias0 = b1s[col]; bias1 = b1s[col + 1]; }
                long node0 = base + rowbase + ms * 16;
                if (node0 < nnodes)
                    *(__half2*)(dsth + node0 * (long)ND + col) =
                        __floats2half2_rn(acc[ms][ns][0] + bias0, acc[ms][ns][1] + bias1);
                long node1 = node0 + 8;
                if (node1 < nnodes)
                    *(__half2*)(dsth + node1 * (long)ND + col) =
                        __floats2half2_rn(acc[ms][ns][2] + bias0, acc[ms][ns][3] + bias1);
            }
        }

        CP_WAIT0();
        __syncthreads();
    }
}

// ---------------------------------------------------------------------------
// Stage 2: 4 lanes/edge, 8 edges/warp, fp16 rows (256 B). Lane t reads chunk
// i*4+t -> 4 lanes cover 64 contiguous bytes per instruction.
// ---------------------------------------------------------------------------
__global__ __launch_bounds__(256) void edge_kernel(
    const int* __restrict__ ei,        // [2, E] int32
    const float* __restrict__ W2,      // [128, 2]
    const float* __restrict__ b2,      // [2]
    float* __restrict__ out,           // [E, 2]
    int E)
{
    __shared__ float w2a[ND];
    __shared__ float w2b[ND];
    const int tid = threadIdx.x;
    if (tid < ND) {
        w2a[tid] = W2[tid * 2 + 0];
        w2b[tid] = W2[tid * 2 + 1];
    }
    __syncthreads();

    const int lane = tid & 31;
    const int t    = lane & 3;
    const int sub  = lane >> 2;
    const float b20 = __ldg(b2), b21 = __ldg(b2 + 1);
    const __half2 z2 = __float2half2_rn(0.f);

    const int warp   = (blockIdx.x * blockDim.x + tid) >> 5;
    const int nwarps = (gridDim.x * blockDim.x) >> 5;

    const float4* wa4 = (const float4*)w2a;
    const float4* wb4 = (const float4*)w2b;

    for (int eb = warp * 8; eb < E; eb += nwarps * 8) {
        const int e = eb + sub;       // E % 8 == 0
        const int r = __ldg(ei + e);
        const int c = __ldg(ei + (size_t)E + e);

        const uint4* pa = (const uint4*)(g_Ah + (size_t)r * ND);
        const uint4* pb = (const uint4*)(g_Bh + (size_t)c * ND);

        float o0 = 0.f, o1 = 0.f;
        #pragma unroll
        for (int i = 0; i < 4; i++) {
            const int ch = i * 4 + t;              // contiguous across 4 lanes
            uint4 a4 = __ldg(pa + ch);
            uint4 b4 = __ldg(pb + ch);
            const float4 walo = wa4[ch * 2], wahi = wa4[ch * 2 + 1];
            const float4 wblo = wb4[ch * 2], wbhi = wb4[ch * 2 + 1];

            const __half2* ap = (const __half2*)&a4;
            const __half2* bp = (const __half2*)&b4;

            float2 f0 = __half22float2(__hmax2(__hadd2(ap[0], bp[0]), z2));
            float2 f1 = __half22float2(__hmax2(__hadd2(ap[1], bp[1]), z2));
            float2 f2 = __half22float2(__hmax2(__hadd2(ap[2], bp[2]), z2));
            float2 f3 = __half22float2(__hmax2(__hadd2(ap[3], bp[3]), z2));

            o0 = fmaf(f0.x, walo.x, fmaf(f0.y, walo.y, o0));
            o0 = fmaf(f1.x, walo.z, fmaf(f1.y, walo.w, o0));
            o0 = fmaf(f2.x, wahi.x, fmaf(f2.y, wahi.y, o0));
            o0 = fmaf(f3.x, wahi.z, fmaf(f3.y, wahi.w, o0));

            o1 = fmaf(f0.x, wblo.x, fmaf(f0.y, wblo.y, o1));
            o1 = fmaf(f1.x, wblo.z, fmaf(f1.y, wblo.w, o1));
            o1 = fmaf(f2.x, wbhi.x, fmaf(f2.y, wbhi.y, o1));
            o1 = fmaf(f3.x, wbhi.z, fmaf(f3.y, wbhi.w, o1));
        }

        o0 += __shfl_xor_sync(0xFFFFFFFFu, o0, 1);
        o0 += __shfl_xor_sync(0xFFFFFFFFu, o0, 2);
        o1 += __shfl_xor_sync(0xFFFFFFFFu, o1, 1);
        o1 += __shfl_xor_sync(0xFFFFFFFFu, o1, 2);

        if (t == 0) {
            *(float2*)(out + 2 * (size_t)e) = make_float2(o0 + b20, o1 + b21);
        }
    }
}

// ---------------------------------------------------------------------------
extern "C" void kernel_launch(void* const* d_in, const int* in_sizes, int n_in,
                              void* d_out, int out_size)
{
    const float* x  = (const float*)d_in[0];      // [N,128]
    const int*   ei = (const int*)d_in[1];        // [2,E] int32
    const float* W1 = (const float*)d_in[2];      // [256,128]
    const float* b1 = (const float*)d_in[3];      // [128]
    const float* W2 = (const float*)d_in[4];      // [128,2]
    const float* b2 = (const float*)d_in[5];      // [2]
    float*       out = (float*)d_out;             // [E,2]

    const int nnodes = in_sizes[0] / ND;
    const int E      = in_sizes[1] / 2;
    const int ntiles = (nnodes + TILE_M - 1) / TILE_M;

    cudaFuncSetAttribute(gemm_kernel, cudaFuncAttributeMaxDynamicSharedMemorySize,
                         SMEM_TOTAL);

    gemm_kernel<<<148, 512, SMEM_TOTAL>>>(x, W1, b1, nnodes, ntiles);
    edge_kernel<<<(E + 63) / 64, 256>>>(ei, W2, b2, out, E);
}